// round 9
// baseline (speedup 1.0000x reference)
#include <cuda_runtime.h>
#include <math.h>

// ---------------- problem constants ----------------
#define M_SAMP 102400
#define NCOIL  12
#define NG     640          // oversampled grid
#define NH     320          // image size
#define NP     645          // padded grid dim (halo: -2..642)
#define NTX    40           // tiles per axis (16x16 cells)
#define NBINS  (NTX*NTX)    // 1600

#define PI_D 3.14159265358979323846
#define BETA_D (PI_D * 4.4102154142094819)   /* pi*sqrt(19.45) */

// padded smem indexing to avoid strided bank conflicts (FFT kernels)
#define PHYS(i) ((i) + ((i) >> 2))

// ---------------- static device scratch ----------------
__device__ float2 g_final[NP * NP * NCOIL];  // padded final grid [k2+2][kr+2][c] (39.9MB)
__device__ float2 g_mid  [NCOIL * NG * NG];  // after pass A: [c][k2][r]
__device__ float2 g_T128[96];                // W128^k
__device__ float2 g_T640[512];               // W640^e
__device__ float  g_S[NH];                   // apod reciprocal * 1/sqrt(640)
__device__ int    g_hist[NBINS];
__device__ int    g_cursor[NBINS];
__device__ int    g_off[NBINS + 1];
__device__ int    g_sorted[M_SAMP];

__constant__ float2 c_W5[5] = {
    { 1.0f,                 0.0f                },
    { 0.30901699437494745f,-0.9510565162951535f },
    {-0.80901699437494745f,-0.5877852522924731f },
    {-0.80901699437494745f, 0.5877852522924731f },
    { 0.30901699437494745f, 0.9510565162951535f }
};

__device__ __forceinline__ float2 cmul(float2 a, float2 b) {
    return make_float2(a.x*b.x - a.y*b.y, a.x*b.y + a.y*b.x);
}

// sample -> (tx, ty) grid coords; identical ops everywhere it is used
__device__ __forceinline__ void sample_coords(const float* __restrict__ kt, int m,
                                              float& tx, float& ty) {
    const float G2PI = 101.85916357881302f;   // 640/(2*pi)
    tx = __ldg(kt + m) * G2PI;          if (tx < 0.f) tx += 640.f;
    ty = __ldg(kt + M_SAMP + m) * G2PI; if (ty < 0.f) ty += 640.f;
}

__device__ __forceinline__ int sample_bin(const float* __restrict__ kt, int m) {
    float tx, ty;
    sample_coords(kt, m, tx, ty);
    int bx = (int)floorf(tx); if (bx > 639) bx = 639; if (bx < 0) bx = 0;
    int by = (int)floorf(ty); if (by > 639) by = 639; if (by < 0) by = 0;
    return (by >> 4) * NTX + (bx >> 4);
}

// ---------------- kernel 1: tables (+ zero histogram) ----------------
__global__ void prep_kernel() {
    int t = threadIdx.x;   // 640 threads
    if (t < 96) {
        double a = -2.0 * PI_D * (double)t / 128.0;
        g_T128[t] = make_float2((float)cos(a), (float)sin(a));
    }
    if (t < 512) {
        double a = -2.0 * PI_D * (double)t / 640.0;
        g_T640[t] = make_float2((float)cos(a), (float)sin(a));
    }
    for (int i = t; i < NBINS; i += 640) g_hist[i] = 0;
    if (t < NH) {
        float n = (float)t - 160.0f;
        float acc = 0.0f;
        #pragma unroll
        for (int js = -6; js <= 6; ++js) {
            float m = fabsf((float)js) * (1.0f/3.0f);
            float kv = 0.0f;
            if (m <= 1.0f) {
                float arg = fmaxf(1.0f - m*m, 0.0f);
                kv = cyl_bessel_i0f((float)BETA_D * sqrtf(arg)) * (1.0f/6.0f);
            }
            acc += kv * cosf(2.0f * (float)PI_D * (float)js * n / 640.0f);
        }
        g_S[t] = 1.0f / acc * 0.039528470752104741f;   // 1/sqrt(640)
    }
}

// ---------------- sort: histogram, scan, scatter ----------------
__global__ void hist_kernel(const float* __restrict__ kt) {
    int m = blockIdx.x * 256 + threadIdx.x;
    if (m < M_SAMP) atomicAdd(&g_hist[sample_bin(kt, m)], 1);
}

__global__ void scan_kernel() {     // 1024 threads, one CTA
    __shared__ int A[2048], B[2048];
    int t = threadIdx.x;
    A[t]        = (t        < NBINS) ? g_hist[t]        : 0;
    A[t + 1024] = (t + 1024 < NBINS) ? g_hist[t + 1024] : 0;
    __syncthreads();
    int *X = A, *Y = B;
    for (int d = 1; d < 2048; d <<= 1) {
        #pragma unroll
        for (int e = t; e < 2048; e += 1024) {
            int v = X[e] + ((e >= d) ? X[e - d] : 0);
            Y[e] = v;
        }
        __syncthreads();
        int* tmp = X; X = Y; Y = tmp;
    }
    // X = inclusive scan -> exclusive offsets
    #pragma unroll
    for (int e = t; e <= NBINS; e += 1024) {
        int off = (e == 0) ? 0 : X[e - 1];
        g_off[e] = off;
        if (e < NBINS) g_cursor[e] = off;
    }
}

__global__ void scatter_kernel(const float* __restrict__ kt) {
    int m = blockIdx.x * 256 + threadIdx.x;
    if (m < M_SAMP) {
        int pos = atomicAdd(&g_cursor[sample_bin(kt, m)], 1);
        g_sorted[pos] = m;
    }
}

// ---------------- radix-4 Stockham work item ----------------
__device__ __forceinline__ void r4_item(const float2* X, float2* Y, int w, int s) {
    int sub = w >> 5;
    int bb  = w & 31;
    int q   = bb & (s - 1);
    int ps  = bb - q;            // p*s
    int bi  = sub * 128;
    float2 x0 = X[PHYS(bi + bb)];
    float2 x1 = X[PHYS(bi + bb + 32)];
    float2 x2 = X[PHYS(bi + bb + 64)];
    float2 x3 = X[PHYS(bi + bb + 96)];
    float2 A = make_float2(x0.x + x2.x, x0.y + x2.y);
    float2 B = make_float2(x1.x + x3.x, x1.y + x3.y);
    float2 C = make_float2(x0.x - x2.x, x0.y - x2.y);
    float2 D = make_float2(x1.x - x3.x, x1.y - x3.y);
    float2 E = make_float2(D.y, -D.x);              // -i*D
    float2 w1 = g_T128[ps];
    float2 w2 = g_T128[2*ps];
    float2 w3 = g_T128[3*ps];
    int o = bi + 4*ps + q;
    Y[PHYS(o)]       = make_float2(A.x + B.x, A.y + B.y);
    Y[PHYS(o + s)]   = cmul(make_float2(C.x + E.x, C.y + E.y), w1);
    Y[PHYS(o + 2*s)] = cmul(make_float2(A.x - B.x, A.y - B.y), w2);
    Y[PHYS(o + 3*s)] = cmul(make_float2(C.x - E.x, C.y - E.y), w3);
}

// 640-pt FFT on decimated data in A; RESULT left in A (PHYS-indexed, natural order)
__device__ __forceinline__ void fft_line_stage(float2* A, float2* B, int lane) {
    float2 *X = A, *Y = B;
    #pragma unroll
    for (int st = 0; st < 3; ++st) {
        int s = 1 << (2*st);
        r4_item(X, Y, lane, s);
        if (lane < 32) r4_item(X, Y, 128 + lane, s);
        __syncthreads();
        float2* t = X; X = Y; Y = t;
    }
    int l6 = lane & 63;
    float2 v[5];
    #pragma unroll
    for (int j = 0; j < 5; ++j) {
        float2 u = X[PHYS(j*128 + l6)];
        float2 w = X[PHYS(j*128 + l6 + 64)];
        float2 f = (lane < 64) ? make_float2(u.x + w.x, u.y + w.y)
                               : make_float2(u.x - w.x, u.y - w.y);
        v[j] = cmul(f, g_T640[j * lane]);
    }
    #pragma unroll
    for (int k2 = 0; k2 < 5; ++k2) {
        float2 acc = v[0];
        #pragma unroll
        for (int j = 1; j < 5; ++j) {
            float2 w5 = c_W5[(j * k2) % 5];
            acc.x += v[j].x * w5.x - v[j].y * w5.y;
            acc.y += v[j].x * w5.y + v[j].y * w5.x;
        }
        Y[PHYS(lane + 128 * k2)] = acc;
    }
}

// ---------------- pass A: fused build + column FFT, row-paired float4 store ----------------
__global__ void fftA_kernel(const float* __restrict__ imr, const float* __restrict__ imi,
                            const float* __restrict__ smr, const float* __restrict__ smi) {
    __shared__ float2 SA[2][800];
    __shared__ float2 SB[2][800];
    int tid  = threadIdx.x;
    int lane = tid & 127;
    int ln   = tid >> 7;
    int b    = blockIdx.x;                   // [0, 12*160)
    int coil = b / 160;
    int q    = b - coil * 160;
    int rr   = 2*q + ln;                     // [0,320), pair stays in one half
    int h    = (rr < 160) ? rr + 160 : rr - 160;

    float sh_ = g_S[h];
    const float* smr_c = smr + coil * (NH*NH);
    const float* smi_c = smi + coil * (NH*NH);

    #pragma unroll
    for (int j = 0; j < 5; ++j) {
        int sc = 5 * lane + j;               // shifted column index
        float2 val = make_float2(0.f, 0.f);
        int w = -1;
        if (sc < 160) w = sc + 160;
        else if (sc >= 480) w = sc - 480;
        if (w >= 0) {
            int ii = h * NH + w;
            float ir = imr[ii], ij = imi[ii];
            float sr = smr_c[ii], sj = smi_c[ii];
            float sca = sh_ * g_S[w];
            val.x = (ir*sr - ij*sj) * sca;
            val.y = (ir*sj + ij*sr) * sca;
        }
        SA[ln][PHYS(j*128 + lane)] = val;    // decimated: A[j*128+n1] = x[5*n1+j]
    }
    __syncthreads();
    fft_line_stage(SA[ln], SB[ln], lane);    // result in SA[ln]
    __syncthreads();

    int rr0 = 2*q;
    int r0  = (rr0 < 160) ? rr0 : rr0 + 320;  // even
    float2* gbase = g_mid + coil * (NG*NG) + r0;
    for (int k2 = tid; k2 < NG; k2 += 256) {
        float2 a = SA[0][PHYS(k2)];
        float2 bb = SA[1][PHYS(k2)];
        *reinterpret_cast<float4*>(gbase + k2 * NG) = make_float4(a.x, a.y, bb.x, bb.y);
    }
}

// ---------------- pass B: row FFT, coil-paired float4 store into padded grid ----------------
__global__ void fftB_kernel() {
    __shared__ float2 SA[2][800];
    __shared__ float2 SB[2][800];
    int tid  = threadIdx.x;
    int lane = tid & 127;
    int ln   = tid >> 7;
    int b    = blockIdx.x;                   // [0, 640*6)
    int k2   = b / 6;
    int cp   = b - k2 * 6;
    int coil = 2*cp + ln;
    const float2* gin = g_mid + (coil * NG + k2) * NG;

    #pragma unroll
    for (int j = 0; j < 5; ++j) {
        int sc = 5 * lane + j;
        float2 val = make_float2(0.f, 0.f);
        if (sc < 160 || sc >= 480) val = __ldg(&gin[sc]);
        SA[ln][PHYS(j*128 + lane)] = val;
    }
    __syncthreads();
    fft_line_stage(SA[ln], SB[ln], lane);    // result in SA[ln]
    __syncthreads();

    float2* gbase = g_final + ((k2 + 2) * NP + 2) * NCOIL + 2*cp;
    for (int kr = tid; kr < NG; kr += 256) {
        float2 a = SA[0][PHYS(kr)];
        float2 bb = SA[1][PHYS(kr)];
        *reinterpret_cast<float4*>(gbase + kr * NCOIL) = make_float4(a.x, a.y, bb.x, bb.y);
    }
}

// ---------------- halo fill: wrap-copy interior into padded borders ----------------
__global__ void halo_kernel() {
    int cell = blockIdx.x * 256 + threadIdx.x;
    if (cell >= 6425) return;
    int yp, xp;
    if (cell < 1290) {                 // top 2 full rows
        yp = cell / NP; xp = cell - yp * NP;
    } else if (cell < 3225) {          // bottom 3 full rows
        int c2 = cell - 1290;
        yp = 642 + c2 / NP; xp = c2 - (c2 / NP) * NP;
    } else {                           // middle 640 rows x 5 halo cols
        int c3 = cell - 3225;
        yp = 2 + c3 / 5;
        int qq = c3 - (c3 / 5) * 5;
        xp = (qq < 2) ? qq : 640 + qq;
    }
    int ys = yp - 2; if (ys < 0) ys += 640; else if (ys >= 640) ys -= 640;
    int xs = xp - 2; if (xs < 0) xs += 640; else if (xs >= 640) xs -= 640;
    const float4* src = reinterpret_cast<const float4*>(g_final + ((ys+2) * NP + (xs+2)) * NCOIL);
    float4*       dst = reinterpret_cast<float4*>(g_final + (yp * NP + xp) * NCOIL);
    #pragma unroll
    for (int i = 0; i < 6; ++i) dst[i] = src[i];
}

// ---------------- interp: CTA per 16x16 tile, smem-staged window ----------------
#define WIN 21
#define WROW (WIN * NCOIL)          // 252 float2 per window row
#define WELEM (WIN * WROW)          // 5292
__global__ void interp_kernel(const float* __restrict__ kt, float2* __restrict__ out) {
    __shared__ float2 W[WELEM + 340];   // slack for pathological edge rounding
    int b   = blockIdx.x;               // tile id
    int ty0 = (b / NTX) * 16;
    int tx0 = (b % NTX) * 16;
    int tid = threadIdx.x;

    // stage window: grid cells y in [ty0-2, ty0+18], x in [tx0-2, tx0+18]
    // padded row index = y + 2  ->  rows ty0 .. ty0+20, cols tx0 .. tx0+20
    {
        const float2* gsrc = g_final + (ty0 * NP + tx0) * NCOIL;
        float4*       wdst = reinterpret_cast<float4*>(W);
        for (int i = tid; i < WIN * (WROW/2); i += 256) {
            int row = i / (WROW/2);
            int col = i - row * (WROW/2);
            wdst[row * (WROW/2) + col] =
                *reinterpret_cast<const float4*>(gsrc + row * (NP*NCOIL) + 2*col);
        }
    }
    int r0 = g_off[b], r1 = g_off[b + 1];
    __syncthreads();

    const float BETA_F = (float)BETA_D;
    const unsigned FULL = 0xffffffffu;
    int lane = tid & 31;
    int wid  = tid >> 5;
    int c    = lane >> 1;
    int h    = lane & 1;
    bool act = (lane < 24);

    for (int i = r0 + wid; i < r1; i += 8) {
        int m = g_sorted[i];
        float tx, ty;
        sample_coords(kt, m, tx, ty);
        float bx = floorf(tx), by = floorf(ty);

        float kv = 0.f;
        if (lane < 12) {
            bool isx = lane < 6;
            int  sl  = isx ? lane : lane - 6;
            float t  = isx ? tx : ty;
            float bq = isx ? bx : by;
            float u  = t - (bq + (float)(sl - 2));
            float mm = fabsf(u) * (1.f/3.f);
            float arg = fmaxf(1.f - mm*mm, 0.f);
            kv = (mm <= 1.f) ? cyl_bessel_i0f(BETA_F * sqrtf(arg)) * (1.f/6.f) : 0.f;
        }
        float wxl[3], wyl[6];
        #pragma unroll
        for (int t = 0; t < 3; ++t) wxl[t] = __shfl_sync(FULL, kv, h*3 + t);
        #pragma unroll
        for (int j = 0; j < 6; ++j) wyl[j] = __shfl_sync(FULL, kv, 6 + j);

        int dx = (int)bx - tx0;
        int dy = (int)by - ty0;
        // tap (tt=h*3+t, j): W[(dy+j)*WROW + (dx+h*3+t)*NCOIL + c]
        const float2* base = W + dy * WROW + (dx + h*3) * NCOIL + (act ? c : 0);

        float re = 0.f, im = 0.f;
        if (act) {
            #pragma unroll
            for (int j = 0; j < 6; ++j) {
                const float2* rowp = base + j * WROW;
                #pragma unroll
                for (int t = 0; t < 3; ++t) {
                    float2 g = rowp[t * NCOIL];
                    float w = wxl[t] * wyl[j];
                    re = fmaf(w, g.x, re);
                    im = fmaf(w, g.y, im);
                }
            }
        }
        re += __shfl_xor_sync(FULL, re, 1);
        im += __shfl_xor_sync(FULL, im, 1);
        if (act && h == 0) out[c * M_SAMP + m] = make_float2(re, im);
    }
}

// ---------------- launch ----------------
extern "C" void kernel_launch(void* const* d_in, const int* in_sizes, int n_in,
                              void* d_out, int out_size) {
    const float* imr = (const float*)d_in[0];
    const float* imi = (const float*)d_in[1];
    const float* smr = (const float*)d_in[2];
    const float* smi = (const float*)d_in[3];
    const float* kt  = (const float*)d_in[4];

    prep_kernel<<<1, 640>>>();
    hist_kernel<<<M_SAMP / 256, 256>>>(kt);
    scan_kernel<<<1, 1024>>>();
    scatter_kernel<<<M_SAMP / 256, 256>>>(kt);
    fftA_kernel<<<NCOIL * 160, 256>>>(imr, imi, smr, smi);   // 1920 CTAs, 2 rows each
    fftB_kernel<<<NG * 6, 256>>>();                          // 3840 CTAs, 2 coils each
    halo_kernel<<<26, 256>>>();
    interp_kernel<<<NBINS, 256>>>(kt, (float2*)d_out);
}

// round 14
// speedup vs baseline: 1.1750x; 1.1750x over previous
#include <cuda_runtime.h>
#include <math.h>

// ---------------- problem constants ----------------
#define M_SAMP 102400
#define NCOIL  12
#define NG     640          // oversampled grid
#define NH     320          // image size
#define NP     645          // padded grid dim (halo: -2..642)

#define PI_D 3.14159265358979323846
#define BETA_D (PI_D * 4.4102154142094819)   /* pi*sqrt(19.45) */

// padded smem indexing to avoid strided bank conflicts
#define PHYS(i) ((i) + ((i) >> 2))

// ---------------- static device scratch ----------------
__device__ float2 g_final[NP * NP * NCOIL];  // padded final grid [yp][xp][c] (39.9MB)
__device__ float2 g_mid  [NCOIL * NG * NG];  // after pass A: [c][k2][r]
__device__ float2 g_T128[96];                // W128^k
__device__ float2 g_T640[512];               // W640^e
__device__ float  g_S[NH];                   // apod reciprocal * 1/sqrt(640)

__constant__ float2 c_W5[5] = {
    { 1.0f,                 0.0f                },
    { 0.30901699437494745f,-0.9510565162951535f },
    {-0.80901699437494745f,-0.5877852522924731f },
    {-0.80901699437494745f, 0.5877852522924731f },
    { 0.30901699437494745f, 0.9510565162951535f }
};

__device__ __forceinline__ float2 cmul(float2 a, float2 b) {
    return make_float2(a.x*b.x - a.y*b.y, a.x*b.y + a.y*b.x);
}

// ---------------- kernel 1: tables ----------------
__global__ void prep_kernel() {
    int t = threadIdx.x;   // 640 threads
    if (t < 96) {
        double a = -2.0 * PI_D * (double)t / 128.0;
        g_T128[t] = make_float2((float)cos(a), (float)sin(a));
    }
    if (t < 512) {
        double a = -2.0 * PI_D * (double)t / 640.0;
        g_T640[t] = make_float2((float)cos(a), (float)sin(a));
    }
    if (t < NH) {
        float n = (float)t - 160.0f;
        float acc = 0.0f;
        #pragma unroll
        for (int js = -6; js <= 6; ++js) {
            float m = fabsf((float)js) * (1.0f/3.0f);
            float kv = 0.0f;
            if (m <= 1.0f) {
                float arg = fmaxf(1.0f - m*m, 0.0f);
                kv = cyl_bessel_i0f((float)BETA_D * sqrtf(arg)) * (1.0f/6.0f);
            }
            acc += kv * cosf(2.0f * (float)PI_D * (float)js * n / 640.0f);
        }
        g_S[t] = 1.0f / acc * 0.039528470752104741f;   // 1/sqrt(640)
    }
}

// ---------------- radix-4 Stockham work item ----------------
__device__ __forceinline__ void r4_item(const float2* X, float2* Y, int w, int s) {
    int sub = w >> 5;
    int bb  = w & 31;
    int q   = bb & (s - 1);
    int ps  = bb - q;            // p*s
    int bi  = sub * 128;
    float2 x0 = X[PHYS(bi + bb)];
    float2 x1 = X[PHYS(bi + bb + 32)];
    float2 x2 = X[PHYS(bi + bb + 64)];
    float2 x3 = X[PHYS(bi + bb + 96)];
    float2 A = make_float2(x0.x + x2.x, x0.y + x2.y);
    float2 B = make_float2(x1.x + x3.x, x1.y + x3.y);
    float2 C = make_float2(x0.x - x2.x, x0.y - x2.y);
    float2 D = make_float2(x1.x - x3.x, x1.y - x3.y);
    float2 E = make_float2(D.y, -D.x);              // -i*D
    float2 w1 = g_T128[ps];
    float2 w2 = g_T128[2*ps];
    float2 w3 = g_T128[3*ps];
    int o = bi + 4*ps + q;
    Y[PHYS(o)]       = make_float2(A.x + B.x, A.y + B.y);
    Y[PHYS(o + s)]   = cmul(make_float2(C.x + E.x, C.y + E.y), w1);
    Y[PHYS(o + 2*s)] = cmul(make_float2(A.x - B.x, A.y - B.y), w2);
    Y[PHYS(o + 3*s)] = cmul(make_float2(C.x - E.x, C.y - E.y), w3);
}

// 640-pt FFT on decimated data in A; RESULT left in A (PHYS-indexed, natural order)
__device__ __forceinline__ void fft_line_stage(float2* A, float2* B, int lane) {
    float2 *X = A, *Y = B;
    #pragma unroll
    for (int st = 0; st < 3; ++st) {
        int s = 1 << (2*st);
        r4_item(X, Y, lane, s);
        if (lane < 32) r4_item(X, Y, 128 + lane, s);
        __syncthreads();
        float2* t = X; X = Y; Y = t;
    }
    int l6 = lane & 63;
    float2 v[5];
    #pragma unroll
    for (int j = 0; j < 5; ++j) {
        float2 u = X[PHYS(j*128 + l6)];
        float2 w = X[PHYS(j*128 + l6 + 64)];
        float2 f = (lane < 64) ? make_float2(u.x + w.x, u.y + w.y)
                               : make_float2(u.x - w.x, u.y - w.y);
        v[j] = cmul(f, g_T640[j * lane]);
    }
    #pragma unroll
    for (int k2 = 0; k2 < 5; ++k2) {
        float2 acc = v[0];
        #pragma unroll
        for (int j = 1; j < 5; ++j) {
            float2 w5 = c_W5[(j * k2) % 5];
            acc.x += v[j].x * w5.x - v[j].y * w5.y;
            acc.y += v[j].x * w5.y + v[j].y * w5.x;
        }
        Y[PHYS(lane + 128 * k2)] = acc;
    }
}

// ---------------- pass A: fused build + column FFT, 4 adjacent rows/CTA (512 thr) -------------
__global__ void fftA_kernel(const float* __restrict__ imr, const float* __restrict__ imi,
                            const float* __restrict__ smr, const float* __restrict__ smi) {
    __shared__ float2 SA[4][800];
    __shared__ float2 SB[4][800];
    int tid  = threadIdx.x;
    int lane = tid & 127;
    int ln   = tid >> 7;                     // 0..3
    int b    = blockIdx.x;                   // [0, 12*80)
    int coil = b / 80;
    int q    = b - coil * 80;
    int rr   = 4*q + ln;                     // [0,320); quad stays in one half (160 % 4 == 0)
    int h    = (rr < 160) ? rr + 160 : rr - 160;

    float sh_ = g_S[h];
    const float* smr_c = smr + coil * (NH*NH);
    const float* smi_c = smi + coil * (NH*NH);

    #pragma unroll
    for (int j = 0; j < 5; ++j) {
        int sc = 5 * lane + j;               // shifted column index
        float2 val = make_float2(0.f, 0.f);
        int w = -1;
        if (sc < 160) w = sc + 160;
        else if (sc >= 480) w = sc - 480;
        if (w >= 0) {
            int ii = h * NH + w;
            float ir = imr[ii], ij = imi[ii];
            float sr = smr_c[ii], sj = smi_c[ii];
            float sca = sh_ * g_S[w];
            val.x = (ir*sr - ij*sj) * sca;
            val.y = (ir*sj + ij*sr) * sca;
        }
        SA[ln][PHYS(j*128 + lane)] = val;    // decimated: A[j*128+n1] = x[5*n1+j]
    }
    __syncthreads();
    fft_line_stage(SA[ln], SB[ln], lane);    // result in SA[ln]
    __syncthreads();

    // cooperative 32B store: rows r0..r0+3 at column k2 -> g_mid[(coil*NG+k2)*NG + r0..r0+3]
    int rr0 = 4*q;
    int r0  = (rr0 < 160) ? rr0 : rr0 + 320;  // divisible by 4
    float2* gbase = g_mid + coil * (NG*NG) + r0;
    for (int k2 = tid; k2 < NG; k2 += 512) {
        float2 a0 = SA[0][PHYS(k2)];
        float2 a1 = SA[1][PHYS(k2)];
        float2 a2 = SA[2][PHYS(k2)];
        float2 a3 = SA[3][PHYS(k2)];
        *reinterpret_cast<float4*>(gbase + k2 * NG)     = make_float4(a0.x, a0.y, a1.x, a1.y);
        *reinterpret_cast<float4*>(gbase + k2 * NG + 2) = make_float4(a2.x, a2.y, a3.x, a3.y);
    }
}

// ---------------- pass B: row FFT, 4 coils/CTA (512 thr), 32B stores into padded grid ---------
__global__ void fftB_kernel() {
    __shared__ float2 SA[4][800];
    __shared__ float2 SB[4][800];
    int tid  = threadIdx.x;
    int lane = tid & 127;
    int ln   = tid >> 7;                     // 0..3
    int b    = blockIdx.x;                   // [0, 640*3)
    int k2   = b / 3;
    int cq   = b - k2 * 3;
    int coil = 4*cq + ln;
    const float2* gin = g_mid + (coil * NG + k2) * NG;

    #pragma unroll
    for (int j = 0; j < 5; ++j) {
        int sc = 5 * lane + j;
        float2 val = make_float2(0.f, 0.f);
        if (sc < 160 || sc >= 480) val = __ldg(&gin[sc]);
        SA[ln][PHYS(j*128 + lane)] = val;
    }
    __syncthreads();
    fft_line_stage(SA[ln], SB[ln], lane);    // result in SA[ln]
    __syncthreads();

    // store cell (yp=k2+2, xp=kr+2), coils 4cq..4cq+3 (32B contiguous)
    float2* gbase = g_final + ((k2 + 2) * NP + 2) * NCOIL + 4*cq;
    for (int kr = tid; kr < NG; kr += 512) {
        float2 a0 = SA[0][PHYS(kr)];
        float2 a1 = SA[1][PHYS(kr)];
        float2 a2 = SA[2][PHYS(kr)];
        float2 a3 = SA[3][PHYS(kr)];
        *reinterpret_cast<float4*>(gbase + kr * NCOIL)     = make_float4(a0.x, a0.y, a1.x, a1.y);
        *reinterpret_cast<float4*>(gbase + kr * NCOIL + 2) = make_float4(a2.x, a2.y, a3.x, a3.y);
    }
}

// ---------------- halo fill: one thread per (halo cell, coil pair) ----------------
__global__ void halo_kernel() {
    int idx = blockIdx.x * 256 + threadIdx.x;   // [0, 6425*6)
    if (idx >= 6425 * 6) return;
    int cell = idx / 6;
    int cp   = idx - cell * 6;
    int yp, xp;
    if (cell < 1290) {                 // top 2 full rows
        yp = cell / NP; xp = cell - yp * NP;
    } else if (cell < 3225) {          // bottom 3 full rows
        int c2 = cell - 1290;
        yp = 642 + c2 / NP; xp = c2 - (c2 / NP) * NP;
    } else {                           // middle 640 rows x 5 halo cols
        int c3 = cell - 3225;
        yp = 2 + c3 / 5;
        int qq = c3 - (c3 / 5) * 5;
        xp = (qq < 2) ? qq : 640 + qq;
    }
    int ys = yp - 2; if (ys < 0) ys += 640; else if (ys >= 640) ys -= 640;
    int xs = xp - 2; if (xs < 0) xs += 640; else if (xs >= 640) xs -= 640;
    const float4* src = reinterpret_cast<const float4*>(g_final + ((ys+2) * NP + (xs+2)) * NCOIL);
    float4*       dst = reinterpret_cast<float4*>(g_final + (yp * NP + xp) * NCOIL);
    dst[cp] = src[cp];
}

// ---------------- KB interpolation: warp per sample, halo grid (R6-identical) ----------------
__global__ void interp_kernel(const float* __restrict__ kt, float2* __restrict__ out) {
    int m    = blockIdx.x * 8 + (threadIdx.x >> 5);
    int lane = threadIdx.x & 31;

    const float BETA_F = (float)BETA_D;
    const float G2PI   = 101.85916357881302f;   // 640/(2*pi)
    const unsigned FULL = 0xffffffffu;

    float om1 = __ldg(kt + m);
    float om2 = __ldg(kt + M_SAMP + m);
    float tx = om1 * G2PI; if (tx < 0.f) tx += 640.f;
    float ty = om2 * G2PI; if (ty < 0.f) ty += 640.f;
    float bx = floorf(tx), by = floorf(ty);

    // KB kernel values: lanes 0..5 -> x taps, 6..11 -> y taps
    float kv = 0.f;
    if (lane < 12) {
        bool isx = lane < 6;
        int  sl  = isx ? lane : lane - 6;
        float t  = isx ? tx : ty;
        float bq = isx ? bx : by;
        float u  = t - (bq + (float)(sl - 2));
        float mm = fabsf(u) * (1.f/3.f);
        float arg = fmaxf(1.f - mm*mm, 0.f);
        kv = (mm <= 1.f) ? cyl_bessel_i0f(BETA_F * sqrtf(arg)) * (1.f/6.f) : 0.f;
    }

    int c   = lane >> 1;          // coil
    int h   = lane & 1;           // x half: taps h*3..h*3+2
    bool act = (lane < 24);

    float wxl[3], wyl[6];
    #pragma unroll
    for (int t = 0; t < 3; ++t) wxl[t] = __shfl_sync(FULL, kv, h*3 + t);
    #pragma unroll
    for (int j = 0; j < 6; ++j) wyl[j] = __shfl_sync(FULL, kv, 6 + j);

    // base: padded grid, tap (t'=h*3+t, j) at base + j*NP*12 + t'*12 (c + h*36 folds t' base)
    int bxi = (int)bx, byi = (int)by;
    const float2* p = g_final + (byi * NP + bxi) * NCOIL + (act ? (c + h*36) : 0);

    float re = 0.f, im = 0.f;
    if (act) {
        #pragma unroll
        for (int j = 0; j < 6; ++j) {
            #pragma unroll
            for (int t = 0; t < 3; ++t) {
                float2 g = __ldg(p + j * (NP*NCOIL) + t * NCOIL);
                float w = wxl[t] * wyl[j];
                re = fmaf(w, g.x, re);
                im = fmaf(w, g.y, im);
            }
        }
    }
    re += __shfl_xor_sync(FULL, re, 1);
    im += __shfl_xor_sync(FULL, im, 1);
    if (act && h == 0) out[c * M_SAMP + m] = make_float2(re, im);
}

// ---------------- launch ----------------
extern "C" void kernel_launch(void* const* d_in, const int* in_sizes, int n_in,
                              void* d_out, int out_size) {
    const float* imr = (const float*)d_in[0];
    const float* imi = (const float*)d_in[1];
    const float* smr = (const float*)d_in[2];
    const float* smi = (const float*)d_in[3];
    const float* kt  = (const float*)d_in[4];

    prep_kernel<<<1, 640>>>();
    fftA_kernel<<<NCOIL * 80, 512>>>(imr, imi, smr, smi);    // 960 CTAs, 4 rows each
    fftB_kernel<<<NG * 3, 512>>>();                          // 1920 CTAs, 4 coils each
    halo_kernel<<<(6425 * 6 + 255) / 256, 256>>>();          // 151 CTAs
    interp_kernel<<<M_SAMP / 8, 256>>>(kt, (float2*)d_out);
}

// round 15
// speedup vs baseline: 1.2377x; 1.0534x over previous
#include <cuda_runtime.h>
#include <math.h>

// ---------------- problem constants ----------------
#define M_SAMP 102400
#define NCOIL  12
#define NG     640          // oversampled grid
#define NH     320          // image size
#define NP     645          // padded grid dim (halo: -2..642)

#define PI_D 3.14159265358979323846
#define BETA_D (PI_D * 4.4102154142094819)   /* pi*sqrt(19.45) */

// padded smem indexing to avoid strided bank conflicts
#define PHYS(i) ((i) + ((i) >> 2))

// ---------------- static device scratch ----------------
__device__ float2 g_final[NP * NP * NCOIL];  // padded final grid [yp][xp][c] (39.9MB)
__device__ float2 g_mid  [NCOIL * NG * NG];  // after pass A: [c][k2][r]
__device__ float2 g_T128[96];                // W128^k
__device__ float2 g_T640[512];               // W640^e
__device__ float  g_S[NH];                   // apod reciprocal * 1/sqrt(640)

__constant__ float2 c_W5[5] = {
    { 1.0f,                 0.0f                },
    { 0.30901699437494745f,-0.9510565162951535f },
    {-0.80901699437494745f,-0.5877852522924731f },
    {-0.80901699437494745f, 0.5877852522924731f },
    { 0.30901699437494745f, 0.9510565162951535f }
};

__device__ __forceinline__ float2 cmul(float2 a, float2 b) {
    return make_float2(a.x*b.x - a.y*b.y, a.x*b.y + a.y*b.x);
}

// ---------------- kernel 1: tables ----------------
__global__ void prep_kernel() {
    int t = threadIdx.x;   // 640 threads
    if (t < 96) {
        double a = -2.0 * PI_D * (double)t / 128.0;
        g_T128[t] = make_float2((float)cos(a), (float)sin(a));
    }
    if (t < 512) {
        double a = -2.0 * PI_D * (double)t / 640.0;
        g_T640[t] = make_float2((float)cos(a), (float)sin(a));
    }
    if (t < NH) {
        float n = (float)t - 160.0f;
        float acc = 0.0f;
        #pragma unroll
        for (int js = -6; js <= 6; ++js) {
            float m = fabsf((float)js) * (1.0f/3.0f);
            float kv = 0.0f;
            if (m <= 1.0f) {
                float arg = fmaxf(1.0f - m*m, 0.0f);
                kv = cyl_bessel_i0f((float)BETA_D * sqrtf(arg)) * (1.0f/6.0f);
            }
            acc += kv * cosf(2.0f * (float)PI_D * (float)js * n / 640.0f);
        }
        g_S[t] = 1.0f / acc * 0.039528470752104741f;   // 1/sqrt(640)
    }
}

// ---------------- radix-4 Stockham work item ----------------
__device__ __forceinline__ void r4_item(const float2* X, float2* Y, int w, int s) {
    int sub = w >> 5;
    int bb  = w & 31;
    int q   = bb & (s - 1);
    int ps  = bb - q;            // p*s
    int bi  = sub * 128;
    float2 x0 = X[PHYS(bi + bb)];
    float2 x1 = X[PHYS(bi + bb + 32)];
    float2 x2 = X[PHYS(bi + bb + 64)];
    float2 x3 = X[PHYS(bi + bb + 96)];
    float2 A = make_float2(x0.x + x2.x, x0.y + x2.y);
    float2 B = make_float2(x1.x + x3.x, x1.y + x3.y);
    float2 C = make_float2(x0.x - x2.x, x0.y - x2.y);
    float2 D = make_float2(x1.x - x3.x, x1.y - x3.y);
    float2 E = make_float2(D.y, -D.x);              // -i*D
    float2 w1 = g_T128[ps];
    float2 w2 = g_T128[2*ps];
    float2 w3 = g_T128[3*ps];
    int o = bi + 4*ps + q;
    Y[PHYS(o)]       = make_float2(A.x + B.x, A.y + B.y);
    Y[PHYS(o + s)]   = cmul(make_float2(C.x + E.x, C.y + E.y), w1);
    Y[PHYS(o + 2*s)] = cmul(make_float2(A.x - B.x, A.y - B.y), w2);
    Y[PHYS(o + 3*s)] = cmul(make_float2(C.x - E.x, C.y - E.y), w3);
}

// 640-pt FFT on decimated data in A; RESULT left in A (PHYS-indexed, natural order)
__device__ __forceinline__ void fft_line_stage(float2* A, float2* B, int lane) {
    float2 *X = A, *Y = B;
    #pragma unroll
    for (int st = 0; st < 3; ++st) {
        int s = 1 << (2*st);
        r4_item(X, Y, lane, s);
        if (lane < 32) r4_item(X, Y, 128 + lane, s);
        __syncthreads();
        float2* t = X; X = Y; Y = t;
    }
    int l6 = lane & 63;
    float2 v[5];
    #pragma unroll
    for (int j = 0; j < 5; ++j) {
        float2 u = X[PHYS(j*128 + l6)];
        float2 w = X[PHYS(j*128 + l6 + 64)];
        float2 f = (lane < 64) ? make_float2(u.x + w.x, u.y + w.y)
                               : make_float2(u.x - w.x, u.y - w.y);
        v[j] = cmul(f, g_T640[j * lane]);
    }
    #pragma unroll
    for (int k2 = 0; k2 < 5; ++k2) {
        float2 acc = v[0];
        #pragma unroll
        for (int j = 1; j < 5; ++j) {
            float2 w5 = c_W5[(j * k2) % 5];
            acc.x += v[j].x * w5.x - v[j].y * w5.y;
            acc.y += v[j].x * w5.y + v[j].y * w5.x;
        }
        Y[PHYS(lane + 128 * k2)] = acc;
    }
}

// ---------------- pass A: fused build + column FFT, row-paired float4 store ----------------
__global__ void fftA_kernel(const float* __restrict__ imr, const float* __restrict__ imi,
                            const float* __restrict__ smr, const float* __restrict__ smi) {
    __shared__ float2 SA[2][800];
    __shared__ float2 SB[2][800];
    int tid  = threadIdx.x;
    int lane = tid & 127;
    int ln   = tid >> 7;
    int b    = blockIdx.x;                   // [0, 12*160)
    int coil = b / 160;
    int q    = b - coil * 160;
    int rr   = 2*q + ln;                     // [0,320), pair stays in one half
    int h    = (rr < 160) ? rr + 160 : rr - 160;

    float sh_ = g_S[h];
    const float* smr_c = smr + coil * (NH*NH);
    const float* smi_c = smi + coil * (NH*NH);

    #pragma unroll
    for (int j = 0; j < 5; ++j) {
        int sc = 5 * lane + j;               // shifted column index
        float2 val = make_float2(0.f, 0.f);
        int w = -1;
        if (sc < 160) w = sc + 160;
        else if (sc >= 480) w = sc - 480;
        if (w >= 0) {
            int ii = h * NH + w;
            float ir = imr[ii], ij = imi[ii];
            float sr = smr_c[ii], sj = smi_c[ii];
            float sca = sh_ * g_S[w];
            val.x = (ir*sr - ij*sj) * sca;
            val.y = (ir*sj + ij*sr) * sca;
        }
        SA[ln][PHYS(j*128 + lane)] = val;    // decimated: A[j*128+n1] = x[5*n1+j]
    }
    __syncthreads();
    fft_line_stage(SA[ln], SB[ln], lane);    // result in SA[ln]
    __syncthreads();

    // cooperative float4 store: g_mid[(coil*NG + k2)*NG + r0..r0+1]
    int rr0 = 2*q;
    int r0  = (rr0 < 160) ? rr0 : rr0 + 320;  // even
    float2* gbase = g_mid + coil * (NG*NG) + r0;
    for (int k2 = tid; k2 < NG; k2 += 256) {
        float2 a = SA[0][PHYS(k2)];
        float2 bb = SA[1][PHYS(k2)];
        *reinterpret_cast<float4*>(gbase + k2 * NG) = make_float4(a.x, a.y, bb.x, bb.y);
    }
}

// ---------------- pass B: row FFT, coil-paired float4 store into padded grid ----------------
__global__ void fftB_kernel() {
    __shared__ float2 SA[2][800];
    __shared__ float2 SB[2][800];
    int tid  = threadIdx.x;
    int lane = tid & 127;
    int ln   = tid >> 7;
    int b    = blockIdx.x;                   // [0, 640*6)
    int k2   = b / 6;
    int cp   = b - k2 * 6;
    int coil = 2*cp + ln;
    const float2* gin = g_mid + (coil * NG + k2) * NG;

    #pragma unroll
    for (int j = 0; j < 5; ++j) {
        int sc = 5 * lane + j;
        float2 val = make_float2(0.f, 0.f);
        if (sc < 160 || sc >= 480) val = __ldg(&gin[sc]);
        SA[ln][PHYS(j*128 + lane)] = val;
    }
    __syncthreads();
    fft_line_stage(SA[ln], SB[ln], lane);    // result in SA[ln]
    __syncthreads();

    // cooperative float4 store: g_final[((k2+2)*NP + kr+2)*NCOIL + 2cp..2cp+1]
    float2* gbase = g_final + ((k2 + 2) * NP + 2) * NCOIL + 2*cp;
    for (int kr = tid; kr < NG; kr += 256) {
        float2 a = SA[0][PHYS(kr)];
        float2 bb = SA[1][PHYS(kr)];
        *reinterpret_cast<float4*>(gbase + kr * NCOIL) = make_float4(a.x, a.y, bb.x, bb.y);
    }
}

// ---------------- halo fill: one thread per (halo cell, coil pair) ----------------
__global__ void halo_kernel() {
    int idx = blockIdx.x * 256 + threadIdx.x;   // [0, 6425*6)
    if (idx >= 6425 * 6) return;
    int cell = idx / 6;
    int cp   = idx - cell * 6;
    int yp, xp;
    if (cell < 1290) {                 // top 2 full rows
        yp = cell / NP; xp = cell - yp * NP;
    } else if (cell < 3225) {          // bottom 3 full rows
        int c2 = cell - 1290;
        yp = 642 + c2 / NP; xp = c2 - (c2 / NP) * NP;
    } else {                           // middle 640 rows x 5 halo cols
        int c3 = cell - 3225;
        yp = 2 + c3 / 5;
        int qq = c3 - (c3 / 5) * 5;
        xp = (qq < 2) ? qq : 640 + qq;
    }
    int ys = yp - 2; if (ys < 0) ys += 640; else if (ys >= 640) ys -= 640;
    int xs = xp - 2; if (xs < 0) xs += 640; else if (xs >= 640) xs -= 640;
    const float4* src = reinterpret_cast<const float4*>(g_final + ((ys+2) * NP + (xs+2)) * NCOIL);
    float4*       dst = reinterpret_cast<float4*>(g_final + (yp * NP + xp) * NCOIL);
    dst[cp] = src[cp];
}

// ---------------- KB interpolation: warp per sample, halo grid, immediate offsets ----------------
__global__ void interp_kernel(const float* __restrict__ kt, float2* __restrict__ out) {
    int m    = blockIdx.x * 8 + (threadIdx.x >> 5);
    int lane = threadIdx.x & 31;

    const float BETA_F = (float)BETA_D;
    const float G2PI   = 101.85916357881302f;   // 640/(2*pi)
    const unsigned FULL = 0xffffffffu;

    float om1 = __ldg(kt + m);
    float om2 = __ldg(kt + M_SAMP + m);
    float tx = om1 * G2PI; if (tx < 0.f) tx += 640.f;
    float ty = om2 * G2PI; if (ty < 0.f) ty += 640.f;
    float bx = floorf(tx), by = floorf(ty);

    // KB kernel values: lanes 0..5 -> x taps, 6..11 -> y taps
    float kv = 0.f;
    if (lane < 12) {
        bool isx = lane < 6;
        int  sl  = isx ? lane : lane - 6;
        float t  = isx ? tx : ty;
        float bq = isx ? bx : by;
        float u  = t - (bq + (float)(sl - 2));
        float mm = fabsf(u) * (1.f/3.f);
        float arg = fmaxf(1.f - mm*mm, 0.f);
        kv = (mm <= 1.f) ? cyl_bessel_i0f(BETA_F * sqrtf(arg)) * (1.f/6.f) : 0.f;
    }

    int c   = lane >> 1;          // coil
    int h   = lane & 1;           // x half: taps h*3..h*3+2
    bool act = (lane < 24);

    float wxl[3], wyl[6];
    #pragma unroll
    for (int t = 0; t < 3; ++t) wxl[t] = __shfl_sync(FULL, kv, h*3 + t);
    #pragma unroll
    for (int j = 0; j < 6; ++j) wyl[j] = __shfl_sync(FULL, kv, 6 + j);

    // base: padded grid, tap (t'=h*3+t, j) at base + j*NP*12 + t'*12 (c + h*36 folds t' base)
    int bxi = (int)bx, byi = (int)by;
    const float2* p = g_final + (byi * NP + bxi) * NCOIL + (act ? (c + h*36) : 0);

    float re = 0.f, im = 0.f;
    if (act) {
        #pragma unroll
        for (int j = 0; j < 6; ++j) {
            #pragma unroll
            for (int t = 0; t < 3; ++t) {
                float2 g = __ldg(p + j * (NP*NCOIL) + t * NCOIL);
                float w = wxl[t] * wyl[j];
                re = fmaf(w, g.x, re);
                im = fmaf(w, g.y, im);
            }
        }
    }
    re += __shfl_xor_sync(FULL, re, 1);
    im += __shfl_xor_sync(FULL, im, 1);
    if (act && h == 0) out[c * M_SAMP + m] = make_float2(re, im);
}

// ---------------- launch ----------------
extern "C" void kernel_launch(void* const* d_in, const int* in_sizes, int n_in,
                              void* d_out, int out_size) {
    const float* imr = (const float*)d_in[0];
    const float* imi = (const float*)d_in[1];
    const float* smr = (const float*)d_in[2];
    const float* smi = (const float*)d_in[3];
    const float* kt  = (const float*)d_in[4];

    prep_kernel<<<1, 640>>>();
    fftA_kernel<<<NCOIL * 160, 256>>>(imr, imi, smr, smi);   // 1920 CTAs, 2 rows each
    fftB_kernel<<<NG * 6, 256>>>();                          // 3840 CTAs, 2 coils each
    halo_kernel<<<(6425 * 6 + 255) / 256, 256>>>();          // 151 CTAs
    interp_kernel<<<M_SAMP / 8, 256>>>(kt, (float2*)d_out);
}